// round 1
// baseline (speedup 1.0000x reference)
#include <cuda_runtime.h>
#include <math.h>

#define B_   2
#define S_   2048
#define D_   1024
#define H_   16
#define HD_  64
#define MTOT (B_ * S_)        // 4096

// Scratch (no cudaMalloc allowed): qkv [B,S,3D], att out [B,S,D]
__device__ float g_qkv[MTOT * 3 * D_];   // ~50 MB
__device__ float g_att[MTOT * D_];       // ~17 MB

// ---------------------------------------------------------------------------
// SGEMM: C[M,N] = A[M,K] @ W[K,N] + bias[N]
// BM=BN=64, BK=16, 256 threads, 4x4 register tile per thread.
// As stored transposed [BK][BM] so inner loop is 2x LDS.128 + 16 FFMA.
// M,N,K all multiples of tile sizes for this problem -> no guards.
// ---------------------------------------------------------------------------
__global__ __launch_bounds__(256)
void sgemm_bias(const float* __restrict__ A, const float* __restrict__ W,
                const float* __restrict__ bias, float* __restrict__ C,
                int M, int N, int K) {
    __shared__ float As[16][64];   // [k][m] transposed
    __shared__ float Bs[16][64];   // [k][n]

    const int tid = threadIdx.x;
    const int tx  = tid & 15;      // n-tile coord (0..15)
    const int ty  = tid >> 4;      // m-tile coord (0..15)
    const int m0  = blockIdx.y * 64;
    const int n0  = blockIdx.x * 64;

    // global load mapping
    const int a_row  = tid >> 2;          // 0..63
    const int a_col4 = (tid & 3) * 4;     // 0,4,8,12
    const int b_row  = tid >> 4;          // 0..15
    const int b_col4 = (tid & 15) * 4;    // 0..60

    float acc[4][4] = {};

    for (int k0 = 0; k0 < K; k0 += 16) {
        float4 av = *(const float4*)(A + (m0 + a_row) * K + k0 + a_col4);
        As[a_col4 + 0][a_row] = av.x;
        As[a_col4 + 1][a_row] = av.y;
        As[a_col4 + 2][a_row] = av.z;
        As[a_col4 + 3][a_row] = av.w;
        *(float4*)&Bs[b_row][b_col4] =
            *(const float4*)(W + (k0 + b_row) * N + n0 + b_col4);
        __syncthreads();

#pragma unroll
        for (int kk = 0; kk < 16; kk++) {
            float4 af = *(const float4*)&As[kk][ty * 4];
            float4 bf = *(const float4*)&Bs[kk][tx * 4];
            float ar[4] = {af.x, af.y, af.z, af.w};
            float br[4] = {bf.x, bf.y, bf.z, bf.w};
#pragma unroll
            for (int i = 0; i < 4; i++)
#pragma unroll
                for (int j = 0; j < 4; j++)
                    acc[i][j] += ar[i] * br[j];
        }
        __syncthreads();
    }

    float4 bv = *(const float4*)(bias + n0 + tx * 4);
    float bb[4] = {bv.x, bv.y, bv.z, bv.w};
#pragma unroll
    for (int i = 0; i < 4; i++) {
        int m = m0 + ty * 4 + i;
        float4 ov;
        ov.x = acc[i][0] + bb[0];
        ov.y = acc[i][1] + bb[1];
        ov.z = acc[i][2] + bb[2];
        ov.w = acc[i][3] + bb[3];
        *(float4*)(C + m * N + n0 + tx * 4) = ov;
    }
}

// ---------------------------------------------------------------------------
// Flash attention: one block per (b*H + h, q-tile of 64).
// 256 threads as 16(ty: 4 q-rows each) x 16(tx: 4 cols each).
// Online softmax; P staged through smem for the PV GEMM.
// smem: Qs, Ks, Vs, Ps each 64 x 65 floats = 66560 B dynamic.
// ---------------------------------------------------------------------------
#define LD 65

__global__ __launch_bounds__(256)
void attention_kernel(const float* __restrict__ qkv, float* __restrict__ out) {
    extern __shared__ float smem[];
    float* Qs = smem;
    float* Ks = Qs + 64 * LD;
    float* Vs = Ks + 64 * LD;
    float* Ps = Vs + 64 * LD;

    const int tid = threadIdx.x;
    const int tx = tid & 15;
    const int ty = tid >> 4;
    const int bh = blockIdx.x;
    const int b  = bh / H_;
    const int h  = bh % H_;
    const int q0 = blockIdx.y * 64;

    const float* base = qkv + (long)b * S_ * (3 * D_);
    const int qoff = h * HD_;
    const int koff = D_ + h * HD_;
    const int voff = 2 * D_ + h * HD_;

    // load Q tile: 64 rows x 64 cols, float4 per thread x4
    const int c4 = (tid & 15) * 4;
    const int r0 = tid >> 4;
#pragma unroll
    for (int i = 0; i < 4; i++) {
        int r = r0 + i * 16;
        float4 v = *(const float4*)(base + (long)(q0 + r) * (3 * D_) + qoff + c4);
        Qs[r * LD + c4 + 0] = v.x;
        Qs[r * LD + c4 + 1] = v.y;
        Qs[r * LD + c4 + 2] = v.z;
        Qs[r * LD + c4 + 3] = v.w;
    }

    float m_i[4], l_i[4], o[4][4];
#pragma unroll
    for (int i = 0; i < 4; i++) {
        m_i[i] = -1e30f;
        l_i[i] = 0.f;
#pragma unroll
        for (int j = 0; j < 4; j++) o[i][j] = 0.f;
    }

    const float scale = 0.125f;  // 1/sqrt(64)

    for (int kt = 0; kt < S_ / 64; kt++) {
        const int k0 = kt * 64;
        // load K and V tiles
#pragma unroll
        for (int i = 0; i < 4; i++) {
            int r = r0 + i * 16;
            const float* rowp = base + (long)(k0 + r) * (3 * D_);
            float4 kv = *(const float4*)(rowp + koff + c4);
            Ks[r * LD + c4 + 0] = kv.x;
            Ks[r * LD + c4 + 1] = kv.y;
            Ks[r * LD + c4 + 2] = kv.z;
            Ks[r * LD + c4 + 3] = kv.w;
            float4 vv = *(const float4*)(rowp + voff + c4);
            Vs[r * LD + c4 + 0] = vv.x;
            Vs[r * LD + c4 + 1] = vv.y;
            Vs[r * LD + c4 + 2] = vv.z;
            Vs[r * LD + c4 + 3] = vv.w;
        }
        __syncthreads();

        // scores: s[i][j] = sum_d Q[ty*4+i][d] * K[tx*4+j][d]
        float s[4][4] = {};
#pragma unroll 8
        for (int dd = 0; dd < 64; dd++) {
            float qf[4], kf[4];
#pragma unroll
            for (int i = 0; i < 4; i++) qf[i] = Qs[(ty * 4 + i) * LD + dd];
#pragma unroll
            for (int j = 0; j < 4; j++) kf[j] = Ks[(tx * 4 + j) * LD + dd];
#pragma unroll
            for (int i = 0; i < 4; i++)
#pragma unroll
                for (int j = 0; j < 4; j++)
                    s[i][j] += qf[i] * kf[j];
        }

        // online softmax per q-row (rows ty*4+i; 16 tx lanes share a row)
#pragma unroll
        for (int i = 0; i < 4; i++) {
            float mx = s[i][0] * scale;
#pragma unroll
            for (int j = 1; j < 4; j++) mx = fmaxf(mx, s[i][j] * scale);
#pragma unroll
            for (int off = 8; off >= 1; off >>= 1)
                mx = fmaxf(mx, __shfl_xor_sync(0xffffffffu, mx, off));
            float m_new = fmaxf(m_i[i], mx);
            float alpha = __expf(m_i[i] - m_new);
            float rs = 0.f;
#pragma unroll
            for (int j = 0; j < 4; j++) {
                float p = __expf(s[i][j] * scale - m_new);
                Ps[(ty * 4 + i) * LD + tx * 4 + j] = p;
                rs += p;
            }
#pragma unroll
            for (int off = 8; off >= 1; off >>= 1)
                rs += __shfl_xor_sync(0xffffffffu, rs, off);
            l_i[i] = l_i[i] * alpha + rs;
            m_i[i] = m_new;
#pragma unroll
            for (int j = 0; j < 4; j++) o[i][j] *= alpha;
        }
        __syncthreads();

        // O += P @ V   (o cols = hd dims tx*4+j)
#pragma unroll 8
        for (int kk = 0; kk < 64; kk++) {
            float pf[4], vf[4];
#pragma unroll
            for (int i = 0; i < 4; i++) pf[i] = Ps[(ty * 4 + i) * LD + kk];
#pragma unroll
            for (int j = 0; j < 4; j++) vf[j] = Vs[kk * LD + tx * 4 + j];
#pragma unroll
            for (int i = 0; i < 4; i++)
#pragma unroll
                for (int j = 0; j < 4; j++)
                    o[i][j] += pf[i] * vf[j];
        }
        __syncthreads();
    }

    // write: out[b, q, h*64 + c]
#pragma unroll
    for (int i = 0; i < 4; i++) {
        float inv = 1.f / l_i[i];
        int q = q0 + ty * 4 + i;
#pragma unroll
        for (int j = 0; j < 4; j++)
            out[((long)(b * S_ + q)) * D_ + h * HD_ + tx * 4 + j] = o[i][j] * inv;
    }
}

// ---------------------------------------------------------------------------
extern "C" void kernel_launch(void* const* d_in, const int* in_sizes, int n_in,
                              void* d_out, int out_size) {
    const float* x     = (const float*)d_in[0];
    const float* Wqkv  = (const float*)d_in[1];
    const float* bqkv  = (const float*)d_in[2];
    const float* Wproj = (const float*)d_in[3];
    const float* bproj = (const float*)d_in[4];
    float* out = (float*)d_out;

    float *qkv, *att;
    cudaGetSymbolAddress((void**)&qkv, g_qkv);
    cudaGetSymbolAddress((void**)&att, g_att);

    dim3 blk(256);

    // 1) QKV projection: [4096,1024] @ [1024,3072]
    sgemm_bias<<<dim3(3 * D_ / 64, MTOT / 64), blk>>>(x, Wqkv, bqkv, qkv,
                                                      MTOT, 3 * D_, D_);

    // 2) attention
    const int smem_bytes = 4 * 64 * LD * sizeof(float);  // 66560
    cudaFuncSetAttribute(attention_kernel,
                         cudaFuncAttributeMaxDynamicSharedMemorySize, smem_bytes);
    attention_kernel<<<dim3(B_ * H_, S_ / 64), blk, smem_bytes>>>(qkv, att);

    // 3) output projection: [4096,1024] @ [1024,1024]
    sgemm_bias<<<dim3(D_ / 64, MTOT / 64), blk>>>(att, Wproj, bproj, out,
                                                  MTOT, D_, D_);
}

// round 6
// speedup vs baseline: 1.1365x; 1.1365x over previous
#include <cuda_runtime.h>
#include <math.h>

#define B_   2
#define S_   2048
#define D_   1024
#define H_   16
#define HD_  64
#define MTOT (B_ * S_)        // 4096

// Scratch (__device__ globals; no cudaMalloc allowed)
__device__ float g_qkv[MTOT * 3 * D_];   // ~50 MB
__device__ float g_att[MTOT * D_];       // ~17 MB

// ---------------------------------------------------------------------------
// SGEMM: C[M,N] = A[M,K] @ W[K,N] + bias[N]
// 128x128 block tile, BK=8, 256 threads, 8x8 per thread (split 4+64 subtiles).
// As stored transposed [8][128]; Bs [8][128]. 16 FFMA per LDS.128.
// ---------------------------------------------------------------------------
__global__ __launch_bounds__(256, 2)
void sgemm128(const float* __restrict__ A, const float* __restrict__ W,
              const float* __restrict__ bias, float* __restrict__ C,
              int M, int N, int K) {
    __shared__ float As[8][128];   // [k][m]
    __shared__ float Bs[8][128];   // [k][n]

    const int tid = threadIdx.x;
    const int tx  = tid & 15;      // n
    const int ty  = tid >> 4;      // m
    const int m0  = blockIdx.y * 128;
    const int n0  = blockIdx.x * 128;

    const int arow = tid >> 1;           // 0..127
    const int ac4  = (tid & 1) * 4;      // 0 or 4
    const int brow = tid >> 5;           // 0..7
    const int bc4  = (tid & 31) * 4;     // 0..124

    float acc[2][2][4][4] = {};

    const float* aptr = A + (size_t)(m0 + arow) * K + ac4;
    const float* bptr = W + (size_t)brow * N + n0 + bc4;

    for (int k0 = 0; k0 < K; k0 += 8) {
        float4 av = *(const float4*)(aptr + k0);
        As[ac4 + 0][arow] = av.x;
        As[ac4 + 1][arow] = av.y;
        As[ac4 + 2][arow] = av.z;
        As[ac4 + 3][arow] = av.w;
        *(float4*)&Bs[brow][bc4] = *(const float4*)(bptr + (size_t)k0 * N);
        __syncthreads();

#pragma unroll
        for (int kk = 0; kk < 8; kk++) {
            float4 a0 = *(const float4*)&As[kk][ty * 4];
            float4 a1 = *(const float4*)&As[kk][ty * 4 + 64];
            float4 b0 = *(const float4*)&Bs[kk][tx * 4];
            float4 b1 = *(const float4*)&Bs[kk][tx * 4 + 64];
            float ar[2][4] = {{a0.x, a0.y, a0.z, a0.w}, {a1.x, a1.y, a1.z, a1.w}};
            float br[2][4] = {{b0.x, b0.y, b0.z, b0.w}, {b1.x, b1.y, b1.z, b1.w}};
#pragma unroll
            for (int ai = 0; ai < 2; ai++)
#pragma unroll
                for (int bi = 0; bi < 2; bi++)
#pragma unroll
                    for (int i = 0; i < 4; i++)
#pragma unroll
                        for (int j = 0; j < 4; j++)
                            acc[ai][bi][i][j] += ar[ai][i] * br[bi][j];
        }
        __syncthreads();
    }

    float4 bb[2];
    bb[0] = *(const float4*)(bias + n0 + tx * 4);
    bb[1] = *(const float4*)(bias + n0 + tx * 4 + 64);
#pragma unroll
    for (int ai = 0; ai < 2; ai++)
#pragma unroll
        for (int i = 0; i < 4; i++) {
            int m = m0 + ty * 4 + i + ai * 64;
            float* crow = C + (size_t)m * N + n0;
#pragma unroll
            for (int bi = 0; bi < 2; bi++) {
                float4 v;
                v.x = acc[ai][bi][i][0] + ((const float*)&bb[bi])[0];
                v.y = acc[ai][bi][i][1] + ((const float*)&bb[bi])[1];
                v.z = acc[ai][bi][i][2] + ((const float*)&bb[bi])[2];
                v.w = acc[ai][bi][i][3] + ((const float*)&bb[bi])[3];
                *(float4*)(crow + tx * 4 + bi * 64) = v;
            }
        }
}

// ---------------------------------------------------------------------------
// Flash attention, 128q x 128k score tile, 256 threads, 8x8 per thread.
// Qt/Kt stored transposed [d][row] for float4/broadcast QK reads.
// P stored row-major [q][k]: STS.128 writes, float4 reads along k in PV.
// smem = Qt(64x132) + Kt(64x132) + Vs(128x68) + Ps(128x132) floats = 166 KB.
// ---------------------------------------------------------------------------
#define QLD 132
#define VLD 68
#define PLD 132

__global__ __launch_bounds__(256)
void attention_kernel(const float* __restrict__ qkv, float* __restrict__ out) {
    extern __shared__ float sm[];
    float* Qt = sm;                    // [64][QLD]  (d-major)
    float* Kt = Qt + 64 * QLD;         // [64][QLD]
    float* Vs = Kt + 64 * QLD;         // [128][VLD] (row-major)
    float* Ps = Vs + 128 * VLD;        // [128][PLD] (row-major P[q][k])

    const int tid = threadIdx.x;
    const int tx  = tid & 15;
    const int ty  = tid >> 4;
    const int bh  = blockIdx.x;
    const int b   = bh >> 4;
    const int h   = bh & 15;
    const int q0  = blockIdx.y * 128;

    const float* base = qkv + (size_t)b * S_ * (3 * D_);
    const int qoff = h * HD_;
    const int koff = D_ + h * HD_;
    const int voff = 2 * D_ + h * HD_;

    // loader mapping: row r = tid>>1 (0..127), col block c0 = (tid&1)*32
    const int lr = tid >> 1;
    const int lc = (tid & 1) * 32;

    // load Q tile transposed: Qt[d][q-row]
    {
        const float* qp = base + (size_t)(q0 + lr) * (3 * D_) + qoff + lc;
#pragma unroll
        for (int i = 0; i < 8; i++) {
            float4 v = *(const float4*)(qp + i * 4);
            Qt[(lc + i * 4 + 0) * QLD + lr] = v.x;
            Qt[(lc + i * 4 + 1) * QLD + lr] = v.y;
            Qt[(lc + i * 4 + 2) * QLD + lr] = v.z;
            Qt[(lc + i * 4 + 3) * QLD + lr] = v.w;
        }
    }

    float m_i[2][4], l_i[2][4], o[2][4][4];
#pragma unroll
    for (int qi = 0; qi < 2; qi++)
#pragma unroll
        for (int i = 0; i < 4; i++) {
            m_i[qi][i] = -1e30f;
            l_i[qi][i] = 0.f;
#pragma unroll
            for (int j = 0; j < 4; j++) o[qi][i][j] = 0.f;
        }

    const float scale = 0.125f;   // 1/sqrt(64)

    for (int kt = 0; kt < S_ / 128; kt++) {
        const int k0 = kt * 128;
        // load K transposed + V row-major
        {
            const float* rowp = base + (size_t)(k0 + lr) * (3 * D_);
            const float* kp = rowp + koff + lc;
            const float* vp = rowp + voff + lc;
#pragma unroll
            for (int i = 0; i < 8; i++) {
                float4 kv = *(const float4*)(kp + i * 4);
                Kt[(lc + i * 4 + 0) * QLD + lr] = kv.x;
                Kt[(lc + i * 4 + 1) * QLD + lr] = kv.y;
                Kt[(lc + i * 4 + 2) * QLD + lr] = kv.z;
                Kt[(lc + i * 4 + 3) * QLD + lr] = kv.w;
                *(float4*)&Vs[lr * VLD + lc + i * 4] = *(const float4*)(vp + i * 4);
            }
        }
        __syncthreads();

        // scores s[qi][ki][i][j] : rows ty*4+i+64qi, cols tx*4+j+64ki
        float s[2][2][4][4] = {};
#pragma unroll 8
        for (int dd = 0; dd < 64; dd++) {
            float4 a0 = *(const float4*)&Qt[dd * QLD + ty * 4];
            float4 a1 = *(const float4*)&Qt[dd * QLD + ty * 4 + 64];
            float4 b0 = *(const float4*)&Kt[dd * QLD + tx * 4];
            float4 b1 = *(const float4*)&Kt[dd * QLD + tx * 4 + 64];
            float ar[2][4] = {{a0.x, a0.y, a0.z, a0.w}, {a1.x, a1.y, a1.z, a1.w}};
            float br[2][4] = {{b0.x, b0.y, b0.z, b0.w}, {b1.x, b1.y, b1.z, b1.w}};
#pragma unroll
            for (int qi = 0; qi < 2; qi++)
#pragma unroll
                for (int ki = 0; ki < 2; ki++)
#pragma unroll
                    for (int i = 0; i < 4; i++)
#pragma unroll
                        for (int j = 0; j < 4; j++)
                            s[qi][ki][i][j] += ar[qi][i] * br[ki][j];
        }

        // online softmax per q-row; write P row-major
#pragma unroll
        for (int qi = 0; qi < 2; qi++)
#pragma unroll
            for (int i = 0; i < 4; i++) {
                const int row = ty * 4 + i + qi * 64;
                float mx = -1e30f;
#pragma unroll
                for (int ki = 0; ki < 2; ki++)
#pragma unroll
                    for (int j = 0; j < 4; j++) {
                        s[qi][ki][i][j] *= scale;
                        mx = fmaxf(mx, s[qi][ki][i][j]);
                    }
#pragma unroll
                for (int off = 8; off >= 1; off >>= 1)
                    mx = fmaxf(mx, __shfl_xor_sync(0xffffffffu, mx, off));
                float m_new = fmaxf(m_i[qi][i], mx);
                float alpha = __expf(m_i[qi][i] - m_new);
                float rs = 0.f;
#pragma unroll
                for (int ki = 0; ki < 2; ki++) {
                    float4 pv;
                    pv.x = __expf(s[qi][ki][i][0] - m_new);
                    pv.y = __expf(s[qi][ki][i][1] - m_new);
                    pv.z = __expf(s[qi][ki][i][2] - m_new);
                    pv.w = __expf(s[qi][ki][i][3] - m_new);
                    rs += pv.x + pv.y + pv.z + pv.w;
                    *(float4*)&Ps[row * PLD + tx * 4 + ki * 64] = pv;
                }
#pragma unroll
                for (int off = 8; off >= 1; off >>= 1)
                    rs += __shfl_xor_sync(0xffffffffu, rs, off);
                l_i[qi][i] = l_i[qi][i] * alpha + rs;
                m_i[qi][i] = m_new;
#pragma unroll
                for (int j = 0; j < 4; j++) o[qi][i][j] *= alpha;
            }
        __syncthreads();

        // O += P @ V : o[qi][i][j], d cols tx*4+j
#pragma unroll 4
        for (int kk4 = 0; kk4 < 32; kk4++) {
            float4 vf[4];
#pragma unroll
            for (int t = 0; t < 4; t++)
                vf[t] = *(const float4*)&Vs[(kk4 * 4 + t) * VLD + tx * 4];
#pragma unroll
            for (int qi = 0; qi < 2; qi++)
#pragma unroll
                for (int i = 0; i < 4; i++) {
                    float4 pf = *(const float4*)&Ps[(ty * 4 + i + qi * 64) * PLD + kk4 * 4];
#pragma unroll
                    for (int j = 0; j < 4; j++) {
                        float vj = pf.x * ((const float*)&vf[0])[j]
                                 + pf.y * ((const float*)&vf[1])[j]
                                 + pf.z * ((const float*)&vf[2])[j]
                                 + pf.w * ((const float*)&vf[3])[j];
                        o[qi][i][j] += vj;
                    }
                }
        }
        __syncthreads();
    }

    // write out[b, q, h*64 + d]
#pragma unroll
    for (int qi = 0; qi < 2; qi++)
#pragma unroll
        for (int i = 0; i < 4; i++) {
            const int q = q0 + ty * 4 + i + qi * 64;
            const float inv = 1.f / l_i[qi][i];
            float4 v;
            v.x = o[qi][i][0] * inv;
            v.y = o[qi][i][1] * inv;
            v.z = o[qi][i][2] * inv;
            v.w = o[qi][i][3] * inv;
            *(float4*)(out + ((size_t)(b * S_ + q)) * D_ + h * HD_ + tx * 4) = v;
        }
}

// ---------------------------------------------------------------------------
extern "C" void kernel_launch(void* const* d_in, const int* in_sizes, int n_in,
                              void* d_out, int out_size) {
    const float* x     = (const float*)d_in[0];
    const float* Wqkv  = (const float*)d_in[1];
    const float* bqkv  = (const float*)d_in[2];
    const float* Wproj = (const float*)d_in[3];
    const float* bproj = (const float*)d_in[4];
    float* out = (float*)d_out;

    float *qkv, *att;
    cudaGetSymbolAddress((void**)&qkv, g_qkv);
    cudaGetSymbolAddress((void**)&att, g_att);

    const int attn_smem = (64 * QLD * 2 + 128 * VLD + 128 * PLD) * (int)sizeof(float);
    cudaFuncSetAttribute(attention_kernel,
                         cudaFuncAttributeMaxDynamicSharedMemorySize, attn_smem);

    // 1) QKV projection: [4096,1024] @ [1024,3072]
    sgemm128<<<dim3(3 * D_ / 128, MTOT / 128), 256>>>(x, Wqkv, bqkv, qkv,
                                                      MTOT, 3 * D_, D_);
    // 2) attention
    attention_kernel<<<dim3(B_ * H_, S_ / 128), 256, attn_smem>>>(qkv, att);

    // 3) output projection: [4096,1024] @ [1024,1024]
    sgemm128<<<dim3(D_ / 128, MTOT / 128), 256>>>(att, Wproj, bproj, out,
                                                  MTOT, D_, D_);
}